// round 8
// baseline (speedup 1.0000x reference)
#include <cuda_runtime.h>
#include <stdint.h>
#include <math.h>

#define SEQ_   32768
#define NV_    256
#define NH_    512
#define NR_    256
#define CDK_   5
#define NSWEEP 14

// JAX >= 0.5 default: jax_threefry_partitionable = True
#define JAX_PARTITIONABLE 1

// ---------------------------------------------------------------------------
// Scratch (device globals; allocation-free per harness rules)
// ---------------------------------------------------------------------------
__device__ float g_X   [(size_t)SEQ_ * NR_];
__device__ float g_Ua  [(size_t)SEQ_ * NR_];
__device__ float g_Ub  [(size_t)SEQ_ * NR_];
__device__ float g_bvt [(size_t)SEQ_ * NV_];
__device__ float g_bh1t[(size_t)SEQ_ * NH_];
__device__ float g_bh2t[(size_t)SEQ_ * NH_];
__device__ float g_h   [(size_t)SEQ_ * NH_];
__device__ float g_h1  [(size_t)SEQ_ * NH_];
__device__ float g_h2  [(size_t)SEQ_ * NH_];
__device__ float g_h1s [(size_t)SEQ_ * NH_];
__device__ float g_vs  [(size_t)SEQ_ * NV_];
// 0: sum sp(v_seq)   1: sum sp(v_sample)  2: sum sp(h1)  3: sum sp(h1_sample)
// 4: monitor sum     5: sum v_seq.bvt     6: sum vs.bvt  7: sum (h1-h1s).bh1t
__device__ double g_acc[8];

// ---------------------------------------------------------------------------
// Threefry-2x32 (20 rounds) — exactly JAX's cipher
// ---------------------------------------------------------------------------
__host__ __device__ __forceinline__
void tf2x32(uint32_t k0, uint32_t k1, uint32_t x0, uint32_t x1,
            uint32_t* o0, uint32_t* o1)
{
    uint32_t ks2 = k0 ^ k1 ^ 0x1BD11BDAu;
    x0 += k0; x1 += k1;
#define TF_RND(R) { x0 += x1; x1 = (x1 << (R)) | (x1 >> (32 - (R))); x1 ^= x0; }
    TF_RND(13) TF_RND(15) TF_RND(26) TF_RND(6)
    x0 += k1;  x1 += ks2 + 1u;
    TF_RND(17) TF_RND(29) TF_RND(16) TF_RND(24)
    x0 += ks2; x1 += k0 + 2u;
    TF_RND(13) TF_RND(15) TF_RND(26) TF_RND(6)
    x0 += k0;  x1 += k1 + 3u;
    TF_RND(17) TF_RND(29) TF_RND(16) TF_RND(24)
    x0 += k1;  x1 += ks2 + 4u;
    TF_RND(13) TF_RND(15) TF_RND(26) TF_RND(6)
    x0 += ks2; x1 += k0 + 5u;
#undef TF_RND
    *o0 = x0; *o1 = x1;
}

// jax.random.uniform(key, shape, f32) element at linear index `idx`.
__device__ __forceinline__
float jx_uniform(uint32_t k0, uint32_t k1, uint32_t idx, uint32_t half)
{
    uint32_t bits;
#if JAX_PARTITIONABLE
    uint32_t o0, o1;
    tf2x32(k0, k1, 0u, idx, &o0, &o1);
    bits = o0 ^ o1;
#else
    uint32_t o0, o1;
    if (idx < half) { tf2x32(k0, k1, idx, idx + half, &o0, &o1); bits = o0; }
    else            { tf2x32(k0, k1, idx - half, idx, &o0, &o1); bits = o1; }
#endif
    return __uint_as_float((bits >> 9) | 0x3f800000u) - 1.0f;
}

// ---------------------------------------------------------------------------
// init: zero U_a (Jacobi start) and accumulators
// ---------------------------------------------------------------------------
__global__ void k_init()
{
    size_t i   = (size_t)blockIdx.x * blockDim.x + threadIdx.x;
    size_t tot = (size_t)SEQ_ * NR_;
    size_t str = (size_t)gridDim.x * blockDim.x;
    for (size_t j = i; j < tot; j += str) g_Ua[j] = 0.0f;
    if (i < 8) g_acc[i] = 0.0;
}

// ---------------------------------------------------------------------------
// Fused tiled GEMM:  C[S,N] = A[S,K] @ B  (+ bias_vec[n] + bias_arr[t,n])
//   TRANSB: B source is [N,K] (use B^T); else B is [K,N]
//   shiftA: row t of A reads source row t-1 (row 0 -> zeros)
//   mode  : 0=linear  1=tanh  2=bernoulli(sigmoid) sample (out2 gets p)
//   red   : 0=none  1=sum softplus(z)  2=sum monitor(vmon, p)   -> g_acc[slot]
// ---------------------------------------------------------------------------
#define BM 64
#define BN 64
#define BK 16

template<bool TRANSB>
__global__ void __launch_bounds__(256, 2)
gemm_ep(const float* __restrict__ A, int shiftA,
        const float* __restrict__ Bm, int K, int N,
        const float* __restrict__ bias_vec,
        const float* __restrict__ bias_arr,
        float* __restrict__ outC, float* __restrict__ out2,
        int mode, int red_mode, int slot,
        const float* __restrict__ vmon,
        uint32_t rk0, uint32_t rk1, uint32_t half,
        double* __restrict__ red)
{
    __shared__ float As[BK][BM];
    __shared__ float Bs[BK][BN + 4];

    const int tid = threadIdx.x;
    const int tx  = tid & 15;
    const int ty  = tid >> 4;
    const int rowBase = blockIdx.y * BM;
    const int colBase = blockIdx.x * BN;

    float c[4][4];
#pragma unroll
    for (int i = 0; i < 4; i++)
#pragma unroll
        for (int j = 0; j < 4; j++) c[i][j] = 0.0f;

    for (int kc = 0; kc < K; kc += BK) {
        // A tile (64 rows x 16 k), stored k-major in smem
        {
            int r  = tid >> 2;
            int kq = (tid & 3) << 2;
            int srow = rowBase + r - shiftA;
            float4 v = make_float4(0.f, 0.f, 0.f, 0.f);
            if (srow >= 0)
                v = *reinterpret_cast<const float4*>(A + (size_t)srow * K + kc + kq);
            As[kq + 0][r] = v.x; As[kq + 1][r] = v.y;
            As[kq + 2][r] = v.z; As[kq + 3][r] = v.w;
        }
        // B tile (16 k x 64 n)
        if (TRANSB) {
            int n  = tid >> 2;
            int kq = (tid & 3) << 2;
            float4 v = *reinterpret_cast<const float4*>(
                Bm + (size_t)(colBase + n) * K + kc + kq);
            Bs[kq + 0][n] = v.x; Bs[kq + 1][n] = v.y;
            Bs[kq + 2][n] = v.z; Bs[kq + 3][n] = v.w;
        } else {
            int kk = tid >> 4;
            int nq = (tid & 15) << 2;
            *reinterpret_cast<float4*>(&Bs[kk][nq]) =
                *reinterpret_cast<const float4*>(Bm + (size_t)(kc + kk) * N + colBase + nq);
        }
        __syncthreads();

#pragma unroll
        for (int k = 0; k < BK; k++) {
            float4 a = *reinterpret_cast<const float4*>(&As[k][ty * 4]);
            float4 b = *reinterpret_cast<const float4*>(&Bs[k][tx * 4]);
            c[0][0] += a.x * b.x; c[0][1] += a.x * b.y; c[0][2] += a.x * b.z; c[0][3] += a.x * b.w;
            c[1][0] += a.y * b.x; c[1][1] += a.y * b.y; c[1][2] += a.y * b.z; c[1][3] += a.y * b.w;
            c[2][0] += a.z * b.x; c[2][1] += a.z * b.y; c[2][2] += a.z * b.z; c[2][3] += a.z * b.w;
            c[3][0] += a.w * b.x; c[3][1] += a.w * b.y; c[3][2] += a.w * b.z; c[3][3] += a.w * b.w;
        }
        __syncthreads();
    }

    // ---- epilogue ----
    double local = 0.0;
#pragma unroll
    for (int i = 0; i < 4; i++) {
        int r = rowBase + ty * 4 + i;
#pragma unroll
        for (int j = 0; j < 4; j++) {
            int nn = colBase + tx * 4 + j;
            size_t off = (size_t)r * N + nn;
            float z = c[i][j];
            if (bias_vec) z += bias_vec[nn];
            if (bias_arr) z += bias_arr[off];

            if (red_mode == 1) {  // softplus = max(z,0)+log1p(exp(-|z|))
                local += (double)(fmaxf(z, 0.f) + log1pf(expf(-fabsf(z))));
            }

            if (mode == 0) {
                if (outC) outC[off] = z;
            } else if (mode == 1) {
                outC[off] = tanhf(z);
            } else {  // bernoulli sample
                float p = 1.f / (1.f + expf(-z));
                float u = jx_uniform(rk0, rk1, (uint32_t)off, half);
                outC[off] = (u < p) ? 1.f : 0.f;
                if (out2) out2[off] = p;
                if (red_mode == 2) {
                    float v = vmon[off];
                    local += (double)(v * logf(p + 1e-10f)
                                      + (1.f - v) * logf(1.f - p + 1e-10f));
                }
            }
        }
    }

    if (red_mode) {
        __shared__ double rs[256];
        rs[tid] = local;
        __syncthreads();
        for (int s = 128; s > 0; s >>= 1) {
            if (tid < s) rs[tid] += rs[tid + s];
            __syncthreads();
        }
        if (tid == 0) atomicAdd(&red[slot], rs[0]);
    }
}

// ---------------------------------------------------------------------------
// dot-product reductions for the free-energy bias terms
// ---------------------------------------------------------------------------
__global__ void __launch_bounds__(256)
k_dots(const float* __restrict__ v,   const float* __restrict__ bvt,
       const float* __restrict__ vs,  const float* __restrict__ h1,
       const float* __restrict__ h1s, const float* __restrict__ bh1t,
       double* __restrict__ red)
{
    size_t i0  = (size_t)blockIdx.x * blockDim.x + threadIdx.x;
    size_t str = (size_t)gridDim.x * blockDim.x;
    size_t nv  = (size_t)SEQ_ * NV_;
    size_t nh  = (size_t)SEQ_ * NH_;
    double d5 = 0, d6 = 0, d7 = 0;
    for (size_t i = i0; i < nv; i += str) {
        float b = bvt[i];
        d5 += (double)(v[i]  * b);
        d6 += (double)(vs[i] * b);
    }
    for (size_t i = i0; i < nh; i += str)
        d7 += (double)((h1[i] - h1s[i]) * bh1t[i]);

    __shared__ double s5[256], s6[256], s7[256];
    int t = threadIdx.x;
    s5[t] = d5; s6[t] = d6; s7[t] = d7;
    __syncthreads();
    for (int s = 128; s > 0; s >>= 1) {
        if (t < s) { s5[t] += s5[t+s]; s6[t] += s6[t+s]; s7[t] += s7[t+s]; }
        __syncthreads();
    }
    if (t == 0) {
        atomicAdd(&red[5], s5[0]);
        atomicAdd(&red[6], s6[0]);
        atomicAdd(&red[7], s7[0]);
    }
}

__global__ void k_final(const double* __restrict__ red, float* __restrict__ out)
{
    double cost1 = (-red[5] - red[0] + red[6] + red[1]) / (double)SEQ_;
    double cost2 = (-red[7] - red[2] + red[3]) / (double)SEQ_;
    out[0] = (float)(cost1 + cost2);
    out[1] = (float)(red[4] / (double)SEQ_);
}

// ---------------------------------------------------------------------------
// host
// ---------------------------------------------------------------------------
static inline void launch_gemm(const float* A, int shiftA, const float* B, int transb,
                               int K, int N,
                               const float* bvec, const float* barr,
                               float* outC, float* out2, int mode,
                               int red_mode, int slot, const float* vmon,
                               uint32_t kk0, uint32_t kk1, double* acc)
{
    dim3 grid(N / BN, SEQ_ / BM), blk(256);
    uint32_t half = (uint32_t)(((size_t)SEQ_ * (size_t)N) / 2);
    if (transb)
        gemm_ep<true ><<<grid, blk>>>(A, shiftA, B, K, N, bvec, barr, outC, out2,
                                      mode, red_mode, slot, vmon, kk0, kk1, half, acc);
    else
        gemm_ep<false><<<grid, blk>>>(A, shiftA, B, K, N, bvec, barr, outC, out2,
                                      mode, red_mode, slot, vmon, kk0, kk1, half, acc);
}

extern "C" void kernel_launch(void* const* d_in, const int* in_sizes, int n_in,
                              void* d_out, int out_size)
{
    const float* v_seq = (const float*)d_in[0];
    const float* W1    = (const float*)d_in[1];
    const float* bv    = (const float*)d_in[2];
    const float* bh1   = (const float*)d_in[3];
    const float* W2    = (const float*)d_in[4];
    const float* bh2   = (const float*)d_in[5];
    const float* Wyv   = (const float*)d_in[6];
    const float* Wyh1  = (const float*)d_in[7];
    const float* Wyh2  = (const float*)d_in[8];
    const float* Wvu   = (const float*)d_in[9];
    const float* Wuu   = (const float*)d_in[10];
    const float* bu    = (const float*)d_in[11];
    float* out = (float*)d_out;

    // scratch addresses
    float *X, *Ua, *Ub, *bvt, *bh1t, *bh2t, *h, *h1, *h2, *h1s, *vs;
    double* acc;
    cudaGetSymbolAddress((void**)&X,    g_X);
    cudaGetSymbolAddress((void**)&Ua,   g_Ua);
    cudaGetSymbolAddress((void**)&Ub,   g_Ub);
    cudaGetSymbolAddress((void**)&bvt,  g_bvt);
    cudaGetSymbolAddress((void**)&bh1t, g_bh1t);
    cudaGetSymbolAddress((void**)&bh2t, g_bh2t);
    cudaGetSymbolAddress((void**)&h,    g_h);
    cudaGetSymbolAddress((void**)&h1,   g_h1);
    cudaGetSymbolAddress((void**)&h2,   g_h2);
    cudaGetSymbolAddress((void**)&h1s,  g_h1s);
    cudaGetSymbolAddress((void**)&vs,   g_vs);
    cudaGetSymbolAddress((void**)&acc,  g_acc);

    // ---- JAX key schedule: key(42) -> 10x split(key,3) ----
    uint32_t kk0 = 0u, kk1 = 42u;
    uint32_t K1[10][2], K2[10][2];
    for (int i = 0; i < 10; i++) {
#if JAX_PARTITIONABLE
        uint32_t n0, n1, a0, a1, b0, b1;
        tf2x32(kk0, kk1, 0u, 0u, &n0, &n1);
        tf2x32(kk0, kk1, 0u, 1u, &a0, &a1);
        tf2x32(kk0, kk1, 0u, 2u, &b0, &b1);
        K1[i][0] = a0; K1[i][1] = a1;
        K2[i][0] = b0; K2[i][1] = b1;
        kk0 = n0; kk1 = n1;
#else
        uint32_t o00, o01, o10, o11, o20, o21;
        tf2x32(kk0, kk1, 0u, 3u, &o00, &o01);
        tf2x32(kk0, kk1, 1u, 4u, &o10, &o11);
        tf2x32(kk0, kk1, 2u, 5u, &o20, &o21);
        K1[i][0] = o20; K1[i][1] = o01;
        K2[i][0] = o11; K2[i][1] = o21;
        kk0 = o00; kk1 = o10;
#endif
    }

    k_init<<<1024, 256>>>();

    // X = v_seq @ Wvu + bu
    launch_gemm(v_seq, 0, Wvu, 0, NV_, NR_, bu, nullptr, X, nullptr, 0, 0, 0, nullptr, 0, 0, acc);

    // Jacobi sweeps: U <- tanh(X + shift(U) @ Wuu)
    for (int s = 0; s < NSWEEP; s++) {
        float* in  = (s % 2 == 0) ? Ua : Ub;
        float* out_u = (s % 2 == 0) ? Ub : Ua;
        launch_gemm(in, 1, Wuu, 0, NR_, NR_, nullptr, X, out_u, nullptr, 1, 0, 0, nullptr, 0, 0, acc);
    }
    // final U in Ua (NSWEEP even)

    // time-varying biases from shifted RNN output
    launch_gemm(Ua, 1, Wyv,  1, NR_, NV_, bv,  nullptr, bvt,  nullptr, 0, 0, 0, nullptr, 0, 0, acc);
    launch_gemm(Ua, 1, Wyh1, 1, NR_, NH_, bh1, nullptr, bh1t, nullptr, 0, 0, 0, nullptr, 0, 0, acc);
    launch_gemm(Ua, 1, Wyh2, 1, NR_, NH_, bh2, nullptr, bh2t, nullptr, 0, 0, 0, nullptr, 0, 0, acc);

    // ---- RBM1 CD-5 (splits 0..4). Iter 0 also yields h1 and FE1(v_seq) sp-sum.
    launch_gemm(v_seq, 0, W1, 0, NV_, NH_, nullptr, bh1t, h, h1, 2, 1, 0, nullptr,
                K1[0][0], K1[0][1], acc);
    launch_gemm(h, 0, W1, 1, NH_, NV_, nullptr, bvt, vs, nullptr, 2, 0, 0, nullptr,
                K2[0][0], K2[0][1], acc);
    for (int i = 1; i < CDK_ - 1; i++) {
        launch_gemm(vs, 0, W1, 0, NV_, NH_, nullptr, bh1t, h, nullptr, 2, 0, 0, nullptr,
                    K1[i][0], K1[i][1], acc);
        launch_gemm(h, 0, W1, 1, NH_, NV_, nullptr, bvt, vs, nullptr, 2, 0, 0, nullptr,
                    K2[i][0], K2[i][1], acc);
    }
    // last iter: the v-GEMM also accumulates the monitor with mean_v
    launch_gemm(vs, 0, W1, 0, NV_, NH_, nullptr, bh1t, h, nullptr, 2, 0, 0, nullptr,
                K1[CDK_-1][0], K1[CDK_-1][1], acc);
    launch_gemm(h, 0, W1, 1, NH_, NV_, nullptr, bvt, vs, nullptr, 2, 2, 4, v_seq,
                K2[CDK_-1][0], K2[CDK_-1][1], acc);

    // FE1(v_sample): softplus(vs@W1 + bh1t)
    launch_gemm(vs, 0, W1, 0, NV_, NH_, nullptr, bh1t, nullptr, nullptr, 0, 1, 1, nullptr,
                0, 0, acc);

    // ---- RBM2 CD-5 (splits 5..9). Iter 0 GEMM shares z with FE2(h1) sp-sum.
    launch_gemm(h1, 0, W2, 0, NH_, NH_, nullptr, bh2t, h2, nullptr, 2, 1, 2, nullptr,
                K1[5][0], K1[5][1], acc);
    launch_gemm(h2, 0, W2, 1, NH_, NH_, nullptr, bh1t, h1s, nullptr, 2, 0, 0, nullptr,
                K2[5][0], K2[5][1], acc);
    for (int i = 6; i < 10; i++) {
        launch_gemm(h1s, 0, W2, 0, NH_, NH_, nullptr, bh2t, h2, nullptr, 2, 0, 0, nullptr,
                    K1[i][0], K1[i][1], acc);
        launch_gemm(h2, 0, W2, 1, NH_, NH_, nullptr, bh1t, h1s, nullptr, 2, 0, 0, nullptr,
                    K2[i][0], K2[i][1], acc);
    }

    // FE2(h1_sample): softplus(h1s@W2 + bh2t)
    launch_gemm(h1s, 0, W2, 0, NH_, NH_, nullptr, bh2t, nullptr, nullptr, 0, 1, 3, nullptr,
                0, 0, acc);

    // bias dot terms + finalize
    k_dots<<<2048, 256>>>(v_seq, bvt, vs, h1, h1s, bh1t, acc);
    k_final<<<1, 1>>>(acc, out);
}